// round 5
// baseline (speedup 1.0000x reference)
#include <cuda_runtime.h>
#include <cstdint>

// Problem constants (fixed shapes)
#define BB    16
#define RS    128
#define TT    128          // T = COLS * C, C == 1
#define HH    32
#define GG    96           // 3*H
#define NV    258          // vocab
#define NTOK  (BB*RS*TT)   // 262144
#define WSLOT (GG*HH)      // 3072 floats per transposed weight matrix

// -------- device scratch (static globals: no allocation) --------
__device__ float g_embW[NV*GG];          // W_ih0[:, :64] @ embed^T  -> [258][96]
__device__ float g_W[6*WSLOT];           // 6 transposed matrices [32][96] k-major:
                                         // 0:M (Wih0@Wh2e) 1:whh0 2:wih1 3:whh1 4:wih2 5:whh2
__device__ float g_base[GG];             // b_ih0 + Wih0@b_h2e
__device__ float g_w64[GG];              // Wih0[:,64] (row-pos column)
__device__ float g_h[(size_t)NTOK*HH];   // top-layer GRU outputs [B][R][T][H]
__device__ int   g_prog[RS*BB];          // progress counters, prog[r*16+b] = #t done

// -------- helpers --------
__device__ __forceinline__ float sigf(float x)   { return __fdividef(1.0f, 1.0f + __expf(-x)); }
__device__ __forceinline__ float tanh_f(float x) { return __fdividef(2.0f, 1.0f + __expf(-2.0f*x)) - 1.0f; }

// -------- kernel 0: zero progress flags (needed every launch/replay) --------
__global__ void zero_prog_kernel() {
    int i = blockIdx.x*blockDim.x + threadIdx.x;
    if (i < RS*BB) g_prog[i] = 0;
}

// -------- kernel 1: precompute folded weights --------
__global__ void precompute_kernel(
    const float* __restrict__ emb,   // [258][64]
    const float* __restrict__ wih0,  // [96][65]
    const float* __restrict__ bih0,  // [96]
    const float* __restrict__ wh2e,  // [65][32]
    const float* __restrict__ bh2e,  // [65]
    const float* __restrict__ whh0,  // [96][32]
    const float* __restrict__ wih1,  // [96][32]
    const float* __restrict__ whh1,
    const float* __restrict__ wih2,
    const float* __restrict__ whh2)
{
    int g = threadIdx.x;     // 0..95
    int blk = blockIdx.x;
    if (blk < NV) {
        float s = 0.f;
        #pragma unroll
        for (int e = 0; e < 64; ++e) s = fmaf(wih0[g*65+e], emb[blk*64+e], s);
        g_embW[blk*GG + g] = s;
    } else if (blk == NV) {
        for (int k = 0; k < HH; ++k) {
            float s = 0.f;
            for (int i = 0; i < 65; ++i) s = fmaf(wih0[g*65+i], wh2e[i*HH+k], s);
            g_W[k*GG + g] = s;                       // M transposed (k-major)
        }
        float s = 0.f;
        for (int i = 0; i < 65; ++i) s = fmaf(wih0[g*65+i], bh2e[i], s);
        g_base[g] = bih0[g] + s;
        g_w64[g]  = wih0[g*65 + 64];
    } else {
        int m = blk - NV - 1;   // 0..4
        const float* w = (m==0)?whh0 : (m==1)?wih1 : (m==2)?whh1 : (m==3)?wih2 : whh2;
        for (int k = 0; k < HH; ++k)
            g_W[(1+m)*WSLOT + k*GG + g] = w[g*HH + k];
    }
}

// -------- generic GRU layer (input & hidden are 32-dim, lane j owns index j) --------
__device__ __forceinline__ void gru_layer(
    const float* __restrict__ Wi, const float* __restrict__ Wh,
    float xv, float& h, int j,
    float bir, float biz, float bin, float bhr, float bhz, float bhn)
{
    float ar = bir, az = biz, an = bin;
    float br = bhr, bz = bhz, bn = bhn;
    #pragma unroll
    for (int k = 0; k < 32; ++k) {
        float xk = __shfl_sync(0xffffffffu, xv, k);
        float hk = __shfl_sync(0xffffffffu, h,  k);
        ar = fmaf(Wi[k*96 +      j], xk, ar);
        az = fmaf(Wi[k*96 + 32 + j], xk, az);
        an = fmaf(Wi[k*96 + 64 + j], xk, an);
        br = fmaf(Wh[k*96 +      j], hk, br);
        bz = fmaf(Wh[k*96 + 32 + j], hk, bz);
        bn = fmaf(Wh[k*96 + 64 + j], hk, bn);
    }
    float rg = sigf(ar + br);
    float zg = sigf(az + bz);
    float ng = tanh_f(an + rg*bn);
    h = fmaf(zg, h - ng, ng);    // (1-z)*n + z*h
}

// -------- kernel 2: wavefront GRU --------
// grid = 128 CTAs (one per row), 512 threads (16 warps, one per batch element).
// All CTAs co-resident (128 <= 148 SMs) -> flag-based wavefront is deadlock-free.
__global__ void __launch_bounds__(512, 1) wave_kernel(
    const int*   __restrict__ x,
    const float* __restrict__ bhh0, const float* __restrict__ bih1,
    const float* __restrict__ bhh1, const float* __restrict__ bih2,
    const float* __restrict__ bhh2)
{
    extern __shared__ float sm[];
    float* sW = sm;                // 6*3072 weights
    float* sv = sm + 6*WSLOT;      // 7*96 bias/const vectors
    int tid = threadIdx.x;
    for (int i = tid; i < 6*WSLOT; i += 512) sW[i] = g_W[i];
    if (tid < GG) {
        sv[tid]        = g_base[tid];
        sv[GG + tid]   = g_w64[tid];
        sv[2*GG + tid] = bhh0[tid];
        sv[3*GG + tid] = bih1[tid];
        sv[4*GG + tid] = bhh1[tid];
        sv[5*GG + tid] = bih2[tid];
        sv[6*GG + tid] = bhh2[tid];
    }
    __syncthreads();

    const int r = blockIdx.x;
    const int b = tid >> 5;
    const int j = tid & 31;

    const float* Mt  = sW;
    const float* Wh0 = sW + 1*WSLOT;
    const float* Wi1 = sW + 2*WSLOT;
    const float* Wh1 = sW + 3*WSLOT;
    const float* Wi2 = sW + 4*WSLOT;
    const float* Wh2 = sW + 5*WSLOT;

    const float rowpos = (float)r * (1.0f/64.0f) - 1.0f;
    const float c_r = fmaf(sv[GG +      j], rowpos, sv[     j]);
    const float c_z = fmaf(sv[GG + 32 + j], rowpos, sv[32 + j]);
    const float c_n = fmaf(sv[GG + 64 + j], rowpos, sv[64 + j]);
    const float bh0r = sv[2*GG+j], bh0z = sv[2*GG+32+j], bh0n = sv[2*GG+64+j];
    const float bi1r = sv[3*GG+j], bi1z = sv[3*GG+32+j], bi1n = sv[3*GG+64+j];
    const float bh1r = sv[4*GG+j], bh1z = sv[4*GG+32+j], bh1n = sv[4*GG+64+j];
    const float bi2r = sv[5*GG+j], bi2z = sv[5*GG+32+j], bi2n = sv[5*GG+64+j];
    const float bh2r = sv[6*GG+j], bh2z = sv[6*GG+32+j], bh2n = sv[6*GG+64+j];

    float h0 = 0.f, h1 = 0.f, h2 = 0.f;   // fresh per row (matches reference)

    const int*   xp    = x   + (b*RS + r)*TT;
    float*       outp  = g_h + (size_t)(b*RS + r)*TT*HH;
    const float* prevp = g_h + (size_t)(b*RS + ((r>0)?(r-1):0))*TT*HH;
    volatile int* pf   = (volatile int*)&g_prog[((r>0)?(r-1):0)*BB + b];
    volatile int* pub  = (volatile int*)&g_prog[r*BB + b];

    for (int t = 0; t < TT; ++t) {
        const int tok = xp[t];
        const float* ew = g_embW + tok*GG;
        float ar = c_r + ew[     j];
        float az = c_z + ew[32 + j];
        float an = c_n + ew[64 + j];
        float br = bh0r, bz = bh0z, bn = bh0n;

        if (r > 0) {
            while (*pf <= t) { }       // wait for prev row's step t
            __threadfence();
            float pv = __ldcg(&prevp[t*HH + j]);
            #pragma unroll
            for (int k = 0; k < 32; ++k) {
                float pk = __shfl_sync(0xffffffffu, pv, k);
                float hk = __shfl_sync(0xffffffffu, h0, k);
                ar = fmaf(Mt [k*96 +      j], pk, ar);
                az = fmaf(Mt [k*96 + 32 + j], pk, az);
                an = fmaf(Mt [k*96 + 64 + j], pk, an);
                br = fmaf(Wh0[k*96 +      j], hk, br);
                bz = fmaf(Wh0[k*96 + 32 + j], hk, bz);
                bn = fmaf(Wh0[k*96 + 64 + j], hk, bn);
            }
        } else {
            #pragma unroll
            for (int k = 0; k < 32; ++k) {
                float hk = __shfl_sync(0xffffffffu, h0, k);
                br = fmaf(Wh0[k*96 +      j], hk, br);
                bz = fmaf(Wh0[k*96 + 32 + j], hk, bz);
                bn = fmaf(Wh0[k*96 + 64 + j], hk, bn);
            }
        }
        {
            float rg = sigf(ar + br);
            float zg = sigf(az + bz);
            float ng = tanh_f(an + rg*bn);
            h0 = fmaf(zg, h0 - ng, ng);
        }
        gru_layer(Wi1, Wh1, h0, h1, j, bi1r, bi1z, bi1n, bh1r, bh1z, bh1n);
        gru_layer(Wi2, Wh2, h1, h2, j, bi2r, bi2z, bi2n, bh2r, bh2z, bh2n);

        // publish top-layer output + progress (release pattern)
        outp[t*HH + j] = h2;
        __threadfence();
        __syncwarp();
        if (j == 0) *pub = t + 1;
    }
}

// -------- kernel 3: output projection pred = out @ w_out^T + b_out --------
// warp handles 4 tokens; lane owns vocab columns v = lane + 32k (k<9, guarded)
__global__ void __launch_bounds__(256) proj_kernel(
    const float* __restrict__ wout,   // [258][32]
    const float* __restrict__ bout,   // [258]
    float* __restrict__ pred)         // [262144][258]
{
    __shared__ float ws[32][264];     // [h][v], padded row -> conflict-free
    __shared__ float bs[288];
    int tid = threadIdx.x;
    for (int i = tid; i < NV*HH; i += 256) {
        int v = i >> 5, h = i & 31;   // wout flat = v*32 + h
        ws[h][v] = wout[i];
    }
    for (int i = tid; i < NV; i += 256) bs[i] = bout[i];
    __syncthreads();

    int warp = tid >> 5, lane = tid & 31;
    int tok0 = (blockIdx.x*8 + warp) * 4;

    float hv[4];
    #pragma unroll
    for (int i = 0; i < 4; ++i) hv[i] = g_h[(size_t)(tok0+i)*HH + lane];

    float acc[4][9];
    #pragma unroll
    for (int k = 0; k < 9; ++k) {
        int v = lane + 32*k;
        float bb = (v < NV) ? bs[v] : 0.f;
        #pragma unroll
        for (int i = 0; i < 4; ++i) acc[i][k] = bb;
    }
    #pragma unroll 8
    for (int h = 0; h < 32; ++h) {
        float w[9];
        #pragma unroll
        for (int k = 0; k < 9; ++k) { int v = lane + 32*k; w[k] = (v < NV) ? ws[h][v] : 0.f; }
        #pragma unroll
        for (int i = 0; i < 4; ++i) {
            float hb = __shfl_sync(0xffffffffu, hv[i], h);
            #pragma unroll
            for (int k = 0; k < 9; ++k) acc[i][k] = fmaf(w[k], hb, acc[i][k]);
        }
    }
    #pragma unroll
    for (int i = 0; i < 4; ++i) {
        size_t base = (size_t)(tok0+i)*NV;
        #pragma unroll
        for (int k = 0; k < 9; ++k) { int v = lane + 32*k; if (v < NV) pred[base + v] = acc[i][k]; }
    }
}

// -------- launch --------
extern "C" void kernel_launch(void* const* d_in, const int* in_sizes, int n_in,
                              void* d_out, int out_size)
{
    const int*   x    = (const int*)  d_in[0];
    const float* emb  = (const float*)d_in[1];
    const float* wih0 = (const float*)d_in[2];
    const float* whh0 = (const float*)d_in[3];
    const float* bih0 = (const float*)d_in[4];
    const float* bhh0 = (const float*)d_in[5];
    const float* wih1 = (const float*)d_in[6];
    const float* whh1 = (const float*)d_in[7];
    const float* bih1 = (const float*)d_in[8];
    const float* bhh1 = (const float*)d_in[9];
    const float* wih2 = (const float*)d_in[10];
    const float* whh2 = (const float*)d_in[11];
    const float* bih2 = (const float*)d_in[12];
    const float* bhh2 = (const float*)d_in[13];
    const float* wh2e = (const float*)d_in[14];
    const float* bh2e = (const float*)d_in[15];
    const float* wout = (const float*)d_in[16];
    const float* bout = (const float*)d_in[17];
    float* pred = (float*)d_out;

    const int smem_bytes = (6*WSLOT + 7*GG) * (int)sizeof(float);   // 76416
    cudaFuncSetAttribute(wave_kernel, cudaFuncAttributeMaxDynamicSharedMemorySize, smem_bytes);

    zero_prog_kernel<<<8, 256>>>();
    precompute_kernel<<<NV + 6, GG>>>(emb, wih0, bih0, wh2e, bh2e,
                                      whh0, wih1, whh1, wih2, whh2);
    wave_kernel<<<RS, 512, smem_bytes>>>(x, bhh0, bih1, bhh1, bih2, bhh2);
    proj_kernel<<<NTOK/(8*4), 256>>>(wout, bout, pred);
}